// round 1
// baseline (speedup 1.0000x reference)
#include <cuda_runtime.h>
#include <cstddef>

#define Bn 256
#define Tn 2048
#define Dn 32
#define Hn 8
#define GATES 32

#define NLOG2E  (-1.4426950408889634f)
#define N2LOG2E (-2.8853900817779268f)

// zx scratch: float4(zi,zf,zg,zo) per (b*T+t, k). +64 pad for prefetch over-read.
__device__ float4 g_zx[(size_t)Bn * Tn * Hn + 64];

__device__ __forceinline__ float ex2f(float x) {
    float y; asm("ex2.approx.f32 %0, %1;" : "=f"(y) : "f"(x)); return y;
}
__device__ __forceinline__ float rcpf(float x) {
    float y; asm("rcp.approx.f32 %0, %1;" : "=f"(y) : "f"(x)); return y;
}

// ---------------------------------------------------------------------------
// Kernel 1: zx[b,t,j] = b'[j] + sum_d x[b,t,d] * Wx'[d,j]  (weights pre-scaled)
// One thread per (b,t) row. 128 threads/block -> 128 rows/block.
// ---------------------------------------------------------------------------
__global__ void __launch_bounds__(128) lstm_zx_kernel(
    const float* __restrict__ x,
    const float* __restrict__ Wx,
    const float* __restrict__ b)
{
    __shared__ float ws[Dn * GATES];
    __shared__ float bs[GATES];

    int tid = threadIdx.x;
    for (int i = tid; i < Dn * GATES; i += 128) {
        int j = i & 31;
        float s = (j >= 16 && j < 24) ? N2LOG2E : NLOG2E;
        ws[i] = Wx[i] * s;
    }
    if (tid < 32) {
        float s = (tid >= 16 && tid < 24) ? N2LOG2E : NLOG2E;
        bs[tid] = b[tid] * s;
    }
    __syncthreads();

    int row = blockIdx.x * 128 + tid;   // row in [0, B*T)

    float4 xv[8];
    const float4* xp = reinterpret_cast<const float4*>(x + (size_t)row * Dn);
#pragma unroll
    for (int q = 0; q < 8; q++) xv[q] = xp[q];

    float z[GATES];
#pragma unroll
    for (int j = 0; j < GATES; j++) z[j] = bs[j];

    const float4* ws4 = reinterpret_cast<const float4*>(ws);
#pragma unroll
    for (int q = 0; q < 8; q++) {
        float xd0 = xv[q].x, xd1 = xv[q].y, xd2 = xv[q].z, xd3 = xv[q].w;
#pragma unroll
        for (int dd = 0; dd < 4; dd++) {
            float xd = (dd == 0) ? xd0 : (dd == 1) ? xd1 : (dd == 2) ? xd2 : xd3;
            int d = q * 4 + dd;
#pragma unroll
            for (int jq = 0; jq < 8; jq++) {
                float4 w = ws4[d * 8 + jq];
                z[jq * 4 + 0] = fmaf(xd, w.x, z[jq * 4 + 0]);
                z[jq * 4 + 1] = fmaf(xd, w.y, z[jq * 4 + 1]);
                z[jq * 4 + 2] = fmaf(xd, w.z, z[jq * 4 + 2]);
                z[jq * 4 + 3] = fmaf(xd, w.w, z[jq * 4 + 3]);
            }
        }
    }

    // Regroup: zx4[row, k] = (z_i[k], z_f[k], z_g[k], z_o[k])
    float4* zp = g_zx + (size_t)row * Hn;
#pragma unroll
    for (int k = 0; k < Hn; k++)
        zp[k] = make_float4(z[k], z[8 + k], z[16 + k], z[24 + k]);
}

// ---------------------------------------------------------------------------
// Kernel 2: sequential recurrence. 8 lanes per row (lane owns hidden unit k,
// all 4 gates). 4 rows per warp, 1 warp per block, 64 blocks.
// ---------------------------------------------------------------------------
__device__ __forceinline__ float dot8(const float* w, float z,
    float v0, float v1, float v2, float v3,
    float v4, float v5, float v6, float v7)
{
    float a = fmaf(v0, w[0], z);
    a = fmaf(v1, w[1], a);
    a = fmaf(v2, w[2], a);
    a = fmaf(v3, w[3], a);
    float bq = v4 * w[4];
    bq = fmaf(v5, w[5], bq);
    bq = fmaf(v6, w[6], bq);
    bq = fmaf(v7, w[7], bq);
    return a + bq;
}

__global__ void __launch_bounds__(32) lstm_rec_kernel(
    const float* __restrict__ Wh,
    const float* __restrict__ h0,
    const float* __restrict__ c0,
    float* __restrict__ out)
{
    int lane = threadIdx.x;
    int k = lane & 7;
    int row = blockIdx.x * 4 + (lane >> 3);

    // Pre-scaled Wh columns for this lane's 4 gates
    float whi[8], whf[8], whg[8], who[8];
#pragma unroll
    for (int hh = 0; hh < 8; hh++) {
        const float* wr = Wh + hh * GATES;
        whi[hh] = wr[k]      * NLOG2E;
        whf[hh] = wr[8 + k]  * NLOG2E;
        whg[hh] = wr[16 + k] * N2LOG2E;
        who[hh] = wr[24 + k] * NLOG2E;
    }

    float h = h0[row * Hn + k];
    float c = c0[row * Hn + k];

    const float4* zx = g_zx + (size_t)row * Tn * Hn + k;
    float* op = out + (size_t)row * Tn * Hn + k;

    // Prefetch ring (depth 4) to hide zx DRAM/L2 latency
    float4 zb[4];
#pragma unroll
    for (int p = 0; p < 4; p++) zb[p] = zx[p * Hn];

    for (int t = 0; t < Tn; t += 4) {
#pragma unroll
        for (int u = 0; u < 4; u++) {
            float4 z = zb[u];

            // Broadcast h across the 8-lane group
            float v0 = __shfl_sync(0xffffffffu, h, 0, 8);
            float v1 = __shfl_sync(0xffffffffu, h, 1, 8);
            float v2 = __shfl_sync(0xffffffffu, h, 2, 8);
            float v3 = __shfl_sync(0xffffffffu, h, 3, 8);
            float v4 = __shfl_sync(0xffffffffu, h, 4, 8);
            float v5 = __shfl_sync(0xffffffffu, h, 5, 8);
            float v6 = __shfl_sync(0xffffffffu, h, 6, 8);
            float v7 = __shfl_sync(0xffffffffu, h, 7, 8);

            float zg = dot8(whg, z.z, v0, v1, v2, v3, v4, v5, v6, v7);
            float zi = dot8(whi, z.x, v0, v1, v2, v3, v4, v5, v6, v7);
            float zf = dot8(whf, z.y, v0, v1, v2, v3, v4, v5, v6, v7);
            float zo = dot8(who, z.w, v0, v1, v2, v3, v4, v5, v6, v7);

            // Activations: weights pre-scaled so sigmoid(x)=rcp(1+ex2(z')),
            // tanh(x)=2*rcp(1+ex2(z'))-1. Issue order: g, i, f, o.
            float eg = ex2f(zg);
            float ei = ex2f(zi);
            float ef = ex2f(zf);
            float eo = ex2f(zo);
            float g_ = fmaf(rcpf(1.0f + eg), 2.0f, -1.0f);
            float i_ = rcpf(1.0f + ei);
            float f_ = rcpf(1.0f + ef);
            float o_ = rcpf(1.0f + eo);

            c = fmaf(f_, c, i_ * g_);

            float ec = ex2f(c * N2LOG2E);
            float tc = fmaf(rcpf(1.0f + ec), 2.0f, -1.0f);
            h = o_ * tc;

            op[(t + u) * Hn] = h;

            // Prefetch 4 steps ahead (pad in g_zx covers the over-read)
            zb[u] = zx[(size_t)(t + u + 4) * Hn];
        }
    }

    // Final h, c tails
    out[(size_t)Bn * Tn * Hn + row * Hn + k] = h;
    out[(size_t)Bn * Tn * Hn + (size_t)Bn * Hn + row * Hn + k] = c;
}

// ---------------------------------------------------------------------------
extern "C" void kernel_launch(void* const* d_in, const int* in_sizes, int n_in,
                              void* d_out, int out_size)
{
    // Resolve inputs by element count (robust to ordering):
    // x=B*T*D=16777216, Wx=D*4H=1024, Wh=H*4H=256, b=4H=32, h0/c0=B*H=2048 (h0 first)
    const float* x = nullptr; const float* Wx = nullptr; const float* Wh = nullptr;
    const float* b = nullptr; const float* h0 = nullptr; const float* c0 = nullptr;
    for (int i = 0; i < n_in; i++) {
        int sz = in_sizes[i];
        const float* p = (const float*)d_in[i];
        if (sz == Bn * Tn * Dn)      x = p;
        else if (sz == Dn * 4 * Hn)  Wx = p;
        else if (sz == Hn * 4 * Hn)  Wh = p;
        else if (sz == 4 * Hn)       b = p;
        else if (sz == Bn * Hn) {
            if (!h0) h0 = p; else c0 = p;
        }
    }

    float* out = (float*)d_out;

    lstm_zx_kernel<<<(Bn * Tn) / 128, 128>>>(x, Wx, b);
    lstm_rec_kernel<<<Bn / 4, 32>>>(Wh, h0, c0, out);
}